// round 8
// baseline (speedup 1.0000x reference)
#include <cuda_runtime.h>
#include <cuda_bf16.h>
#include <cuda_fp16.h>
#include <cstdint>

// Problem constants
#define BATCH 8
#define NNODE 2048
#define DIM   256
#define MROWS (BATCH * NNODE)   // 16384

// -------------------- scratch (no allocations allowed) --------------------
__device__ float g_H[(size_t)MROWS * DIM];          // 16 MB fp32 (sproj)
__device__ __half g_Hh[(size_t)MROWS * DIM];        // 8 MB fp16 (gather)
__device__ float g_s1[MROWS];
__device__ float g_s2[MROWS];
__device__ __nv_bfloat16 g_Xhi[(size_t)MROWS * DIM];
__device__ __nv_bfloat16 g_Xlo[(size_t)MROWS * DIM];
__device__ __nv_bfloat16 g_Whi[DIM * DIM];
__device__ __nv_bfloat16 g_Wlo[DIM * DIM];

// ============================================================================
// Helpers (base sm_103 target: ldmatrix + mma.sync + cp.async; NO tcgen05)
// ============================================================================
__device__ __forceinline__ uint32_t smem_u32(const void* p) {
    uint32_t a;
    asm("{ .reg .u64 t; cvta.to.shared.u64 t, %1; cvt.u32.u64 %0, t; }"
        : "=r"(a) : "l"(p));
    return a;
}

__device__ __forceinline__ void cp16(uint32_t dst, const void* src) {
    asm volatile("cp.async.cg.shared.global [%0], [%1], 16;"
                 :: "r"(dst), "l"(src));
}
#define CP_COMMIT() asm volatile("cp.async.commit_group;" ::: "memory")
#define CP_WAIT0()  asm volatile("cp.async.wait_group 0;" ::: "memory")

__device__ __forceinline__ void ldm_x4(uint32_t* r, uint32_t addr) {
    asm volatile("ldmatrix.sync.aligned.m8n8.x4.shared.b16 {%0,%1,%2,%3}, [%4];"
        : "=r"(r[0]), "=r"(r[1]), "=r"(r[2]), "=r"(r[3]) : "r"(addr));
}

__device__ __forceinline__ void mma_bf16(float* c, const uint32_t* a,
                                         const uint32_t* b) {
    asm volatile(
        "mma.sync.aligned.m16n8k16.row.col.f32.bf16.bf16.f32 "
        "{%0,%1,%2,%3}, {%4,%5,%6,%7}, {%8,%9}, {%0,%1,%2,%3};"
        : "+f"(c[0]), "+f"(c[1]), "+f"(c[2]), "+f"(c[3])
        : "r"(a[0]), "r"(a[1]), "r"(a[2]), "r"(a[3]), "r"(b[0]), "r"(b[1]));
}

// bf16 split: hi = bf16(x), lo = bf16(x - hi); packs (e0, e1) pairs.
__device__ __forceinline__ void split_pair(float e0, float e1,
                                           uint32_t& h, uint32_t& l) {
    asm("cvt.rn.bf16x2.f32 %0, %1, %2;" : "=r"(h) : "f"(e1), "f"(e0));
    __nv_bfloat162 hb = *(__nv_bfloat162*)&h;
    float r0 = e0 - __bfloat162float(hb.x);
    float r1 = e1 - __bfloat162float(hb.y);
    asm("cvt.rn.bf16x2.f32 %0, %1, %2;" : "=r"(l) : "f"(r1), "f"(r0));
}

// ============================================================================
// Kernel 0: fp32 -> split-bf16 conversion
// ============================================================================
__global__ void __launch_bounds__(256)
convert_split(const float* __restrict__ src, __nv_bfloat16* __restrict__ hi,
              __nv_bfloat16* __restrict__ lo)
{
    const int idx = blockIdx.x * 256 + threadIdx.x;
    const float* s = src + (size_t)idx * 8;
    float4 v0 = *(const float4*)(s);
    float4 v1 = *(const float4*)(s + 4);
    uint32_t h[4], l[4];
    split_pair(v0.x, v0.y, h[0], l[0]);
    split_pair(v0.z, v0.w, h[1], l[1]);
    split_pair(v1.x, v1.y, h[2], l[2]);
    split_pair(v1.z, v1.w, h[3], l[3]);
    uint4* hp = (uint4*)(hi + (size_t)idx * 8);
    uint4* lp = (uint4*)(lo + (size_t)idx * 8);
    *hp = make_uint4(h[0], h[1], h[2], h[3]);
    *lp = make_uint4(l[0], l[1], l[2], l[3]);
}

// ============================================================================
// Kernel 1: split-bf16 HMMA GEMM (unchanged from round 6/7)
// ============================================================================
#define SROW 24
#define STAGE_B (128 * SROW * 2)

__global__ void __launch_bounds__(256, 1)
gemm_h_mma(const __nv_bfloat16* __restrict__ Xhi,
           const __nv_bfloat16* __restrict__ Xlo,
           const __nv_bfloat16* __restrict__ Whi,
           const __nv_bfloat16* __restrict__ Wlo,
           const float* __restrict__ bias)
{
    __shared__ __nv_bfloat16 sAhi[2][128][SROW];
    __shared__ __nv_bfloat16 sAlo[2][128][SROW];
    __shared__ __nv_bfloat16 sBhi[2][128][SROW];
    __shared__ __nv_bfloat16 sBlo[2][128][SROW];

    const int tid   = threadIdx.x;
    const int wid   = tid >> 5;
    const int lane  = tid & 31;
    const int cta_m = blockIdx.x * 128;
    const int cta_n = blockIdx.y * 128;

    const int wm = (wid & 1) * 64;
    const int wn = (wid >> 1) * 32;

    const int lrow  = tid >> 1;
    const int lhalf = (tid & 1) * 8;
    const __nv_bfloat16* srcAhi = Xhi + (size_t)(cta_m + lrow) * DIM + lhalf;
    const __nv_bfloat16* srcAlo = Xlo + (size_t)(cta_m + lrow) * DIM + lhalf;
    const __nv_bfloat16* srcBhi = Whi + (size_t)(cta_n + lrow) * DIM + lhalf;
    const __nv_bfloat16* srcBlo = Wlo + (size_t)(cta_n + lrow) * DIM + lhalf;
    const uint32_t dAhi = smem_u32(&sAhi[0][lrow][lhalf]);
    const uint32_t dAlo = smem_u32(&sAlo[0][lrow][lhalf]);
    const uint32_t dBhi = smem_u32(&sBhi[0][lrow][lhalf]);
    const uint32_t dBlo = smem_u32(&sBlo[0][lrow][lhalf]);

    uint32_t aAhi[4], aAlo[4];
#pragma unroll
    for (int mt = 0; mt < 4; mt++) {
        int row = wm + mt * 16 + (lane & 15);
        int kh  = (lane >> 4) * 8;
        aAhi[mt] = smem_u32(&sAhi[0][row][kh]);
        aAlo[mt] = smem_u32(&sAlo[0][row][kh]);
    }
    uint32_t bBhi[2], bBlo[2];
#pragma unroll
    for (int nt2 = 0; nt2 < 2; nt2++) {
        int nr = wn + nt2 * 16 + ((lane >> 4) * 8) + (lane & 7);
        int kh = ((lane >> 3) & 1) * 8;
        bBhi[nt2] = smem_u32(&sBhi[0][nr][kh]);
        bBlo[nt2] = smem_u32(&sBlo[0][nr][kh]);
    }

    float acc[4][4][4];
#pragma unroll
    for (int mt = 0; mt < 4; mt++)
#pragma unroll
        for (int nt = 0; nt < 4; nt++)
#pragma unroll
            for (int c = 0; c < 4; c++) acc[mt][nt][c] = 0.f;

    cp16(dAhi, srcAhi); cp16(dAlo, srcAlo);
    cp16(dBhi, srcBhi); cp16(dBlo, srcBlo);
    CP_COMMIT();

#pragma unroll 1
    for (int ks = 0; ks < DIM / 16; ks++) {
        CP_WAIT0();
        __syncthreads();

        if (ks + 1 < DIM / 16) {
            const uint32_t so = (uint32_t)(((ks + 1) & 1) * STAGE_B);
            const int ko = (ks + 1) * 16;
            cp16(dAhi + so, srcAhi + ko); cp16(dAlo + so, srcAlo + ko);
            cp16(dBhi + so, srcBhi + ko); cp16(dBlo + so, srcBlo + ko);
        }
        CP_COMMIT();

        const uint32_t st = (uint32_t)((ks & 1) * STAGE_B);

        uint32_t fAhi[4][4], fAlo[4][4];
#pragma unroll
        for (int mt = 0; mt < 4; mt++) {
            ldm_x4(fAhi[mt], aAhi[mt] + st);
            ldm_x4(fAlo[mt], aAlo[mt] + st);
        }
        uint32_t fBhi[4][2], fBlo[4][2];
#pragma unroll
        for (int nt2 = 0; nt2 < 2; nt2++) {
            uint32_t r[4];
            ldm_x4(r, bBhi[nt2] + st);
            fBhi[nt2 * 2][0] = r[0]; fBhi[nt2 * 2][1] = r[1];
            fBhi[nt2 * 2 + 1][0] = r[2]; fBhi[nt2 * 2 + 1][1] = r[3];
            ldm_x4(r, bBlo[nt2] + st);
            fBlo[nt2 * 2][0] = r[0]; fBlo[nt2 * 2][1] = r[1];
            fBlo[nt2 * 2 + 1][0] = r[2]; fBlo[nt2 * 2 + 1][1] = r[3];
        }

#pragma unroll
        for (int mt = 0; mt < 4; mt++)
#pragma unroll
            for (int nt = 0; nt < 4; nt++) {
                mma_bf16(acc[mt][nt], fAhi[mt], fBhi[nt]);
                mma_bf16(acc[mt][nt], fAhi[mt], fBlo[nt]);
                mma_bf16(acc[mt][nt], fAlo[mt], fBhi[nt]);
            }
    }

    const int gid = lane >> 2;
    const int tig = lane & 3;
#pragma unroll
    for (int nt = 0; nt < 4; nt++) {
        const int col = cta_n + wn + nt * 8 + tig * 2;
        const float2 bv = *(const float2*)(bias + col);
#pragma unroll
        for (int mt = 0; mt < 4; mt++) {
            const int m0 = cta_m + wm + mt * 16 + gid;
            float2 v0 = make_float2(acc[mt][nt][0] + bv.x, acc[mt][nt][1] + bv.y);
            float2 v1 = make_float2(acc[mt][nt][2] + bv.x, acc[mt][nt][3] + bv.y);
            *(float2*)(g_H + (size_t)m0 * DIM + col)       = v0;
            *(float2*)(g_H + (size_t)(m0 + 8) * DIM + col) = v1;
            *(__half2*)(g_Hh + (size_t)m0 * DIM + col)       = __float22half2_rn(v0);
            *(__half2*)(g_Hh + (size_t)(m0 + 8) * DIM + col) = __float22half2_rn(v1);
        }
    }
}

// ============================================================================
// Kernel 2: s1/s2 projections (unchanged)
// ============================================================================
__global__ void __launch_bounds__(256)
sproj_kernel(const float* __restrict__ a1, const float* __restrict__ a2,
             const float* __restrict__ att_b)
{
    const int row  = blockIdx.x * 8 + (threadIdx.x >> 5);
    const int lane = threadIdx.x & 31;
    const float* hr = g_H + (size_t)row * DIM + lane * 8;

    float4 h0 = *(const float4*)(hr);
    float4 h1 = *(const float4*)(hr + 4);
    float4 p0 = *(const float4*)(a1 + lane * 8);
    float4 p1 = *(const float4*)(a1 + lane * 8 + 4);
    float4 q0 = *(const float4*)(a2 + lane * 8);
    float4 q1 = *(const float4*)(a2 + lane * 8 + 4);

    float d1 = h0.x * p0.x + h0.y * p0.y + h0.z * p0.z + h0.w * p0.w
             + h1.x * p1.x + h1.y * p1.y + h1.z * p1.z + h1.w * p1.w;
    float d2 = h0.x * q0.x + h0.y * q0.y + h0.z * q0.z + h0.w * q0.w
             + h1.x * q1.x + h1.y * q1.y + h1.z * q1.z + h1.w * q1.w;

#pragma unroll
    for (int o = 16; o; o >>= 1) {
        d1 += __shfl_xor_sync(0xffffffffu, d1, o);
        d2 += __shfl_xor_sync(0xffffffffu, d2, o);
    }
    if (lane == 0) {
        g_s1[row] = d1 + att_b[0];
        g_s2[row] = d2;
    }
}

// ============================================================================
// Kernel 3: attention + aggregation. ZERO smem atomics:
// per-warp segmented compaction (register count via ballot prefix),
// per-warp row-sums reduced in registers, one __syncthreads between phases.
// ============================================================================
#define CAP 256   // slots per warp segment (absolute worst case)

__global__ void __launch_bounds__(256)
attn_agg_kernel(const float* __restrict__ adj, const float* __restrict__ mask,
                float* __restrict__ out)
{
    const int i   = blockIdx.x;
    const int b   = blockIdx.y;
    const int tid = threadIdx.x;
    const int row = b * NNODE + i;

    __shared__ float wbuf[8 * CAP];      // 8 KB, per-warp segments
    __shared__ int   jbuf[8 * CAP];      // 8 KB
    __shared__ float sred[4][DIM];       // 4 KB
    __shared__ int   s_cnts[8];
    __shared__ float s_sums[8];

    const float mi = mask[row];
    float* orow = out + (size_t)row * DIM;
    if (mi == 0.f) {
        orow[tid] = 0.f;
        return;
    }

    const float* arow = adj + (size_t)row * NNODE;
    const float  s1i  = g_s1[row];
    const float* mrow = mask + b * NNODE;
    const float* s2b  = g_s2 + b * NNODE;
    const int lane = tid & 31;
    const int warp = tid >> 5;

    // ---- Phase A: batched loads, per-warp ballot compaction (no atomics) ----
    float4 av[2], mv[2], sv[2];
#pragma unroll
    for (int u = 0; u < 2; u++) {
        int j0 = tid * 4 + u * 1024;
        av[u] = *(const float4*)(arow + j0);
        mv[u] = *(const float4*)(mrow + j0);
        sv[u] = *(const float4*)(s2b + j0);
    }

    float w[8];
    float psum = 0.f;
#pragma unroll
    for (int u = 0; u < 2; u++) {
        const float* ap = (const float*)&av[u];
        const float* mp = (const float*)&mv[u];
        const float* sp = (const float*)&sv[u];
#pragma unroll
        for (int e = 0; e < 4; e++) {
            float ww = 0.f;
            if (ap[e] != 0.f && mp[e] != 0.f) {
                float lg = s1i + sp[e];
                ww = ap[e] * mp[e] / (1.f + __expf(-lg));
            }
            w[u * 4 + e] = ww;
            psum += ww;
        }
    }

    const unsigned lmask = (1u << lane) - 1u;
    const int segbase = warp * CAP;
    int cnt = 0;                              // uniform across the warp
#pragma unroll
    for (int e = 0; e < 8; e++) {
        unsigned bal = __ballot_sync(0xffffffffu, w[e] != 0.f);
        if (w[e] != 0.f) {
            int rank = __popc(bal & lmask);
            wbuf[segbase + cnt + rank] = w[e];
            jbuf[segbase + cnt + rank] = tid * 4 + (e >> 2) * 1024 + (e & 3);
        }
        cnt += __popc(bal);
    }

#pragma unroll
    for (int o = 16; o; o >>= 1) psum += __shfl_xor_sync(0xffffffffu, psum, o);
    if (lane == 0) {
        s_cnts[warp] = cnt;
        s_sums[warp] = psum;
    }
    __syncthreads();

    // total row-sum (register re-sum; 8 LDS per thread, no atomics)
    float tsum = 0.f;
#pragma unroll
    for (int s = 0; s < 8; s++) tsum += s_sums[s];
    const float inv = 1.f / (tsum + 1e-8f);

    // ---- Phase B: segmented fp16 gather ----
    const __half* Hb = g_Hh + (size_t)b * NNODE * DIM;
    const int g  = tid >> 6;             // neighbor group 0..3
    const int c4 = (tid & 63) * 4;       // channel quad

    float4 acc = make_float4(0.f, 0.f, 0.f, 0.f);
#pragma unroll 1
    for (int seg = 0; seg < 8; seg++) {
        const int c    = s_cnts[seg];
        const int base = seg * CAP;
#pragma unroll 1
        for (int k = g; k < c; k += 4) {
            int   ja = jbuf[base + k];
            float wa = wbuf[base + k];
            uint2 ra = *(const uint2*)(Hb + (size_t)ja * DIM + c4);
            float2 a0 = __half22float2(*(__half2*)&ra.x);
            float2 a1f = __half22float2(*(__half2*)&ra.y);
            acc.x += wa * a0.x;  acc.y += wa * a0.y;
            acc.z += wa * a1f.x; acc.w += wa * a1f.y;
        }
    }

    *(float4*)&sred[g][c4] = acc;
    __syncthreads();

    float r = sred[0][tid] + sred[1][tid] + sred[2][tid] + sred[3][tid];
    orow[tid] = r * inv;
}

// ============================================================================
// Launch
// ============================================================================
extern "C" void kernel_launch(void* const* d_in, const int* in_sizes, int n_in,
                              void* d_out, int out_size)
{
    const float* x     = (const float*)d_in[0];
    const float* adj   = (const float*)d_in[1];
    const float* mask  = (const float*)d_in[2];
    const float* W     = (const float*)d_in[3];
    const float* bias  = (const float*)d_in[4];
    const float* a1    = (const float*)d_in[5];
    const float* a2    = (const float*)d_in[6];
    const float* att_b = (const float*)d_in[7];
    float* out = (float*)d_out;

    __nv_bfloat16 *xhi, *xlo, *whi, *wlo;
    cudaGetSymbolAddress((void**)&xhi, g_Xhi);
    cudaGetSymbolAddress((void**)&xlo, g_Xlo);
    cudaGetSymbolAddress((void**)&whi, g_Whi);
    cudaGetSymbolAddress((void**)&wlo, g_Wlo);

    convert_split<<<(MROWS * DIM) / (256 * 8), 256>>>(x, xhi, xlo);
    convert_split<<<(DIM * DIM) / (256 * 8), 256>>>(W, whi, wlo);

    dim3 g1(MROWS / 128, DIM / 128);      // (128, 2)
    gemm_h_mma<<<g1, 256>>>(xhi, xlo, whi, wlo, bias);

    sproj_kernel<<<MROWS / 8, 256>>>(a1, a2, att_b);

    dim3 g3(NNODE, BATCH);                // (2048, 8)
    attn_agg_kernel<<<g3, 256>>>(adj, mask, out);
}

// round 9
// speedup vs baseline: 1.0760x; 1.0760x over previous
#include <cuda_runtime.h>
#include <cuda_bf16.h>
#include <cuda_fp16.h>
#include <cstdint>

// Problem constants
#define BATCH 8
#define NNODE 2048
#define DIM   256
#define MROWS (BATCH * NNODE)   // 16384

// -------------------- scratch (no allocations allowed) --------------------
__device__ float g_H[(size_t)MROWS * DIM];          // 16 MB fp32 (sproj)
__device__ __half g_Hh[(size_t)MROWS * DIM];        // 8 MB fp16 (gather)
__device__ float g_s1[MROWS];
__device__ float g_s2[MROWS];
__device__ __nv_bfloat16 g_Xhi[(size_t)MROWS * DIM];
__device__ __nv_bfloat16 g_Xlo[(size_t)MROWS * DIM];
__device__ __nv_bfloat16 g_Whi[DIM * DIM];
__device__ __nv_bfloat16 g_Wlo[DIM * DIM];

// ============================================================================
// Helpers (base sm_103 target: ldmatrix + mma.sync + cp.async; NO tcgen05)
// ============================================================================
__device__ __forceinline__ uint32_t smem_u32(const void* p) {
    uint32_t a;
    asm("{ .reg .u64 t; cvta.to.shared.u64 t, %1; cvt.u32.u64 %0, t; }"
        : "=r"(a) : "l"(p));
    return a;
}

__device__ __forceinline__ void cp16(uint32_t dst, const void* src) {
    asm volatile("cp.async.cg.shared.global [%0], [%1], 16;"
                 :: "r"(dst), "l"(src));
}
#define CP_COMMIT() asm volatile("cp.async.commit_group;" ::: "memory")
#define CP_WAIT0()  asm volatile("cp.async.wait_group 0;" ::: "memory")

__device__ __forceinline__ void ldm_x4(uint32_t* r, uint32_t addr) {
    asm volatile("ldmatrix.sync.aligned.m8n8.x4.shared.b16 {%0,%1,%2,%3}, [%4];"
        : "=r"(r[0]), "=r"(r[1]), "=r"(r[2]), "=r"(r[3]) : "r"(addr));
}

__device__ __forceinline__ void mma_bf16(float* c, const uint32_t* a,
                                         const uint32_t* b) {
    asm volatile(
        "mma.sync.aligned.m16n8k16.row.col.f32.bf16.bf16.f32 "
        "{%0,%1,%2,%3}, {%4,%5,%6,%7}, {%8,%9}, {%0,%1,%2,%3};"
        : "+f"(c[0]), "+f"(c[1]), "+f"(c[2]), "+f"(c[3])
        : "r"(a[0]), "r"(a[1]), "r"(a[2]), "r"(a[3]), "r"(b[0]), "r"(b[1]));
}

// bf16 split: hi = bf16(x), lo = bf16(x - hi); packs (e0, e1) pairs.
__device__ __forceinline__ void split_pair(float e0, float e1,
                                           uint32_t& h, uint32_t& l) {
    asm("cvt.rn.bf16x2.f32 %0, %1, %2;" : "=r"(h) : "f"(e1), "f"(e0));
    __nv_bfloat162 hb = *(__nv_bfloat162*)&h;
    float r0 = e0 - __bfloat162float(hb.x);
    float r1 = e1 - __bfloat162float(hb.y);
    asm("cvt.rn.bf16x2.f32 %0, %1, %2;" : "=r"(l) : "f"(r1), "f"(r0));
}

// ============================================================================
// Kernel 0: fp32 -> split-bf16 conversion
// ============================================================================
__global__ void __launch_bounds__(256)
convert_split(const float* __restrict__ src, __nv_bfloat16* __restrict__ hi,
              __nv_bfloat16* __restrict__ lo)
{
    const int idx = blockIdx.x * 256 + threadIdx.x;
    const float* s = src + (size_t)idx * 8;
    float4 v0 = *(const float4*)(s);
    float4 v1 = *(const float4*)(s + 4);
    uint32_t h[4], l[4];
    split_pair(v0.x, v0.y, h[0], l[0]);
    split_pair(v0.z, v0.w, h[1], l[1]);
    split_pair(v1.x, v1.y, h[2], l[2]);
    split_pair(v1.z, v1.w, h[3], l[3]);
    uint4* hp = (uint4*)(hi + (size_t)idx * 8);
    uint4* lp = (uint4*)(lo + (size_t)idx * 8);
    *hp = make_uint4(h[0], h[1], h[2], h[3]);
    *lp = make_uint4(l[0], l[1], l[2], l[3]);
}

// ============================================================================
// Kernel 1: split-bf16 HMMA GEMM (unchanged; dual fp32+fp16 epilogue)
// ============================================================================
#define SROW 24
#define STAGE_B (128 * SROW * 2)

__global__ void __launch_bounds__(256, 1)
gemm_h_mma(const __nv_bfloat16* __restrict__ Xhi,
           const __nv_bfloat16* __restrict__ Xlo,
           const __nv_bfloat16* __restrict__ Whi,
           const __nv_bfloat16* __restrict__ Wlo,
           const float* __restrict__ bias)
{
    __shared__ __nv_bfloat16 sAhi[2][128][SROW];
    __shared__ __nv_bfloat16 sAlo[2][128][SROW];
    __shared__ __nv_bfloat16 sBhi[2][128][SROW];
    __shared__ __nv_bfloat16 sBlo[2][128][SROW];

    const int tid   = threadIdx.x;
    const int wid   = tid >> 5;
    const int lane  = tid & 31;
    const int cta_m = blockIdx.x * 128;
    const int cta_n = blockIdx.y * 128;

    const int wm = (wid & 1) * 64;
    const int wn = (wid >> 1) * 32;

    const int lrow  = tid >> 1;
    const int lhalf = (tid & 1) * 8;
    const __nv_bfloat16* srcAhi = Xhi + (size_t)(cta_m + lrow) * DIM + lhalf;
    const __nv_bfloat16* srcAlo = Xlo + (size_t)(cta_m + lrow) * DIM + lhalf;
    const __nv_bfloat16* srcBhi = Whi + (size_t)(cta_n + lrow) * DIM + lhalf;
    const __nv_bfloat16* srcBlo = Wlo + (size_t)(cta_n + lrow) * DIM + lhalf;
    const uint32_t dAhi = smem_u32(&sAhi[0][lrow][lhalf]);
    const uint32_t dAlo = smem_u32(&sAlo[0][lrow][lhalf]);
    const uint32_t dBhi = smem_u32(&sBhi[0][lrow][lhalf]);
    const uint32_t dBlo = smem_u32(&sBlo[0][lrow][lhalf]);

    uint32_t aAhi[4], aAlo[4];
#pragma unroll
    for (int mt = 0; mt < 4; mt++) {
        int row = wm + mt * 16 + (lane & 15);
        int kh  = (lane >> 4) * 8;
        aAhi[mt] = smem_u32(&sAhi[0][row][kh]);
        aAlo[mt] = smem_u32(&sAlo[0][row][kh]);
    }
    uint32_t bBhi[2], bBlo[2];
#pragma unroll
    for (int nt2 = 0; nt2 < 2; nt2++) {
        int nr = wn + nt2 * 16 + ((lane >> 4) * 8) + (lane & 7);
        int kh = ((lane >> 3) & 1) * 8;
        bBhi[nt2] = smem_u32(&sBhi[0][nr][kh]);
        bBlo[nt2] = smem_u32(&sBlo[0][nr][kh]);
    }

    float acc[4][4][4];
#pragma unroll
    for (int mt = 0; mt < 4; mt++)
#pragma unroll
        for (int nt = 0; nt < 4; nt++)
#pragma unroll
            for (int c = 0; c < 4; c++) acc[mt][nt][c] = 0.f;

    cp16(dAhi, srcAhi); cp16(dAlo, srcAlo);
    cp16(dBhi, srcBhi); cp16(dBlo, srcBlo);
    CP_COMMIT();

#pragma unroll 1
    for (int ks = 0; ks < DIM / 16; ks++) {
        CP_WAIT0();
        __syncthreads();

        if (ks + 1 < DIM / 16) {
            const uint32_t so = (uint32_t)(((ks + 1) & 1) * STAGE_B);
            const int ko = (ks + 1) * 16;
            cp16(dAhi + so, srcAhi + ko); cp16(dAlo + so, srcAlo + ko);
            cp16(dBhi + so, srcBhi + ko); cp16(dBlo + so, srcBlo + ko);
        }
        CP_COMMIT();

        const uint32_t st = (uint32_t)((ks & 1) * STAGE_B);

        uint32_t fAhi[4][4], fAlo[4][4];
#pragma unroll
        for (int mt = 0; mt < 4; mt++) {
            ldm_x4(fAhi[mt], aAhi[mt] + st);
            ldm_x4(fAlo[mt], aAlo[mt] + st);
        }
        uint32_t fBhi[4][2], fBlo[4][2];
#pragma unroll
        for (int nt2 = 0; nt2 < 2; nt2++) {
            uint32_t r[4];
            ldm_x4(r, bBhi[nt2] + st);
            fBhi[nt2 * 2][0] = r[0]; fBhi[nt2 * 2][1] = r[1];
            fBhi[nt2 * 2 + 1][0] = r[2]; fBhi[nt2 * 2 + 1][1] = r[3];
            ldm_x4(r, bBlo[nt2] + st);
            fBlo[nt2 * 2][0] = r[0]; fBlo[nt2 * 2][1] = r[1];
            fBlo[nt2 * 2 + 1][0] = r[2]; fBlo[nt2 * 2 + 1][1] = r[3];
        }

#pragma unroll
        for (int mt = 0; mt < 4; mt++)
#pragma unroll
            for (int nt = 0; nt < 4; nt++) {
                mma_bf16(acc[mt][nt], fAhi[mt], fBhi[nt]);
                mma_bf16(acc[mt][nt], fAhi[mt], fBlo[nt]);
                mma_bf16(acc[mt][nt], fAlo[mt], fBhi[nt]);
            }
    }

    const int gid = lane >> 2;
    const int tig = lane & 3;
#pragma unroll
    for (int nt = 0; nt < 4; nt++) {
        const int col = cta_n + wn + nt * 8 + tig * 2;
        const float2 bv = *(const float2*)(bias + col);
#pragma unroll
        for (int mt = 0; mt < 4; mt++) {
            const int m0 = cta_m + wm + mt * 16 + gid;
            float2 v0 = make_float2(acc[mt][nt][0] + bv.x, acc[mt][nt][1] + bv.y);
            float2 v1 = make_float2(acc[mt][nt][2] + bv.x, acc[mt][nt][3] + bv.y);
            *(float2*)(g_H + (size_t)m0 * DIM + col)       = v0;
            *(float2*)(g_H + (size_t)(m0 + 8) * DIM + col) = v1;
            *(__half2*)(g_Hh + (size_t)m0 * DIM + col)       = __float22half2_rn(v0);
            *(__half2*)(g_Hh + (size_t)(m0 + 8) * DIM + col) = __float22half2_rn(v1);
        }
    }
}

// ============================================================================
// Kernel 2: s1/s2 projections (unchanged)
// ============================================================================
__global__ void __launch_bounds__(256)
sproj_kernel(const float* __restrict__ a1, const float* __restrict__ a2,
             const float* __restrict__ att_b)
{
    const int row  = blockIdx.x * 8 + (threadIdx.x >> 5);
    const int lane = threadIdx.x & 31;
    const float* hr = g_H + (size_t)row * DIM + lane * 8;

    float4 h0 = *(const float4*)(hr);
    float4 h1 = *(const float4*)(hr + 4);
    float4 p0 = *(const float4*)(a1 + lane * 8);
    float4 p1 = *(const float4*)(a1 + lane * 8 + 4);
    float4 q0 = *(const float4*)(a2 + lane * 8);
    float4 q1 = *(const float4*)(a2 + lane * 8 + 4);

    float d1 = h0.x * p0.x + h0.y * p0.y + h0.z * p0.z + h0.w * p0.w
             + h1.x * p1.x + h1.y * p1.y + h1.z * p1.z + h1.w * p1.w;
    float d2 = h0.x * q0.x + h0.y * q0.y + h0.z * q0.z + h0.w * q0.w
             + h1.x * q1.x + h1.y * q1.y + h1.z * q1.z + h1.w * q1.w;

#pragma unroll
    for (int o = 16; o; o >>= 1) {
        d1 += __shfl_xor_sync(0xffffffffu, d1, o);
        d2 += __shfl_xor_sync(0xffffffffu, d2, o);
    }
    if (lane == 0) {
        g_s1[row] = d1 + att_b[0];
        g_s2[row] = d2;
    }
}

// ============================================================================
// Kernel 3: attention + aggregation.
// Phase A: R6-proven block-wide ballot compaction (dense list, smem atomics).
// Phase B: warp-per-neighbor-stride gather — each warp reads a full 512 B
// fp16 H row with ONE coalesced LDG.128 per lane; (j,w) prefetched one
// iteration ahead. Sequential depth ~5 instead of ~10, no fragmentation.
// ============================================================================
__global__ void __launch_bounds__(256)
attn_agg_kernel(const float* __restrict__ adj, const float* __restrict__ mask,
                float* __restrict__ out)
{
    const int i   = blockIdx.x;
    const int b   = blockIdx.y;
    const int tid = threadIdx.x;
    const int row = b * NNODE + i;

    __shared__ float wbuf[NNODE];        // 8 KB dense list
    __shared__ int   jbuf[NNODE];        // 8 KB
    __shared__ float sred[8][DIM];       // 8 KB
    __shared__ int   s_cnt;
    __shared__ float s_sum;

    const float mi = mask[row];
    float* orow = out + (size_t)row * DIM;
    if (mi == 0.f) {
        orow[tid] = 0.f;
        return;
    }

    if (tid == 0) { s_cnt = 0; s_sum = 0.f; }
    __syncthreads();

    const float* arow = adj + (size_t)row * NNODE;
    const float  s1i  = g_s1[row];
    const float* mrow = mask + b * NNODE;
    const float* s2b  = g_s2 + b * NNODE;
    const int lane = tid & 31;
    const int warp = tid >> 5;

    // ---- Phase A (proven R6 form) ----
    float4 av[2], mv[2], sv[2];
#pragma unroll
    for (int u = 0; u < 2; u++) {
        int j0 = tid * 4 + u * 1024;
        av[u] = *(const float4*)(arow + j0);
        mv[u] = *(const float4*)(mrow + j0);
        sv[u] = *(const float4*)(s2b + j0);
    }

    float w[8];
    float psum = 0.f;
#pragma unroll
    for (int u = 0; u < 2; u++) {
        const float* ap = (const float*)&av[u];
        const float* mp = (const float*)&mv[u];
        const float* sp = (const float*)&sv[u];
#pragma unroll
        for (int e = 0; e < 4; e++) {
            float ww = 0.f;
            if (ap[e] != 0.f && mp[e] != 0.f) {
                float lg = s1i + sp[e];
                ww = ap[e] * mp[e] / (1.f + __expf(-lg));
            }
            w[u * 4 + e] = ww;
            psum += ww;
        }
    }

#pragma unroll
    for (int e = 0; e < 8; e++) {
        unsigned bal = __ballot_sync(0xffffffffu, w[e] != 0.f);
        if (bal) {
            int leader = __ffs(bal) - 1;
            int base = 0;
            if (lane == leader) base = atomicAdd(&s_cnt, __popc(bal));
            base = __shfl_sync(0xffffffffu, base, leader);
            if (w[e] != 0.f) {
                int rank = __popc(bal & ((1u << lane) - 1u));
                wbuf[base + rank] = w[e];
                jbuf[base + rank] = tid * 4 + (e >> 2) * 1024 + (e & 3);
            }
        }
    }

#pragma unroll
    for (int o = 16; o; o >>= 1) psum += __shfl_xor_sync(0xffffffffu, psum, o);
    if (lane == 0) atomicAdd(&s_sum, psum);
    __syncthreads();

    // ---- Phase B: warp-strided full-row fp16 gather with prefetch ----
    const int n = s_cnt;
    const float inv = 1.f / (s_sum + 1e-8f);
    const __half* Hb = g_Hh + (size_t)b * NNODE * DIM;
    const int c8 = lane * 8;             // 8 fp16 channels = 16 B per lane

    float acc[8];
#pragma unroll
    for (int c = 0; c < 8; c++) acc[c] = 0.f;

    int k = warp;
    int   jn = 0;
    float wn = 0.f;
    if (k < n) { jn = jbuf[k]; wn = wbuf[k]; }
    while (k < n) {
        const int   j  = jn;
        const float wv = wn;
        const int k2 = k + 8;
        if (k2 < n) { jn = jbuf[k2]; wn = wbuf[k2]; }   // prefetch next (j,w)
        uint4 r = *(const uint4*)(Hb + (size_t)j * DIM + c8);
        float2 f0 = __half22float2(*(__half2*)&r.x);
        float2 f1 = __half22float2(*(__half2*)&r.y);
        float2 f2 = __half22float2(*(__half2*)&r.z);
        float2 f3 = __half22float2(*(__half2*)&r.w);
        acc[0] += wv * f0.x; acc[1] += wv * f0.y;
        acc[2] += wv * f1.x; acc[3] += wv * f1.y;
        acc[4] += wv * f2.x; acc[5] += wv * f2.y;
        acc[6] += wv * f3.x; acc[7] += wv * f3.y;
        k = k2;
    }

    *(float4*)&sred[warp][c8]     = make_float4(acc[0], acc[1], acc[2], acc[3]);
    *(float4*)&sred[warp][c8 + 4] = make_float4(acc[4], acc[5], acc[6], acc[7]);
    __syncthreads();

    float r = 0.f;
#pragma unroll
    for (int s = 0; s < 8; s++) r += sred[s][tid];
    orow[tid] = r * inv;
}

// ============================================================================
// Launch
// ============================================================================
extern "C" void kernel_launch(void* const* d_in, const int* in_sizes, int n_in,
                              void* d_out, int out_size)
{
    const float* x     = (const float*)d_in[0];
    const float* adj   = (const float*)d_in[1];
    const float* mask  = (const float*)d_in[2];
    const float* W     = (const float*)d_in[3];
    const float* bias  = (const float*)d_in[4];
    const float* a1    = (const float*)d_in[5];
    const float* a2    = (const float*)d_in[6];
    const float* att_b = (const float*)d_in[7];
    float* out = (float*)d_out;

    __nv_bfloat16 *xhi, *xlo, *whi, *wlo;
    cudaGetSymbolAddress((void**)&xhi, g_Xhi);
    cudaGetSymbolAddress((void**)&xlo, g_Xlo);
    cudaGetSymbolAddress((void**)&whi, g_Whi);
    cudaGetSymbolAddress((void**)&wlo, g_Wlo);

    convert_split<<<(MROWS * DIM) / (256 * 8), 256>>>(x, xhi, xlo);
    convert_split<<<(DIM * DIM) / (256 * 8), 256>>>(W, whi, wlo);

    dim3 g1(MROWS / 128, DIM / 128);      // (128, 2)
    gemm_h_mma<<<g1, 256>>>(xhi, xlo, whi, wlo, bias);

    sproj_kernel<<<MROWS / 8, 256>>>(a1, a2, att_b);

    dim3 g3(NNODE, BATCH);                // (2048, 8)
    attn_agg_kernel<<<g3, 256>>>(adj, mask, out);
}

// round 10
// speedup vs baseline: 1.1440x; 1.0632x over previous
#include <cuda_runtime.h>
#include <cuda_bf16.h>
#include <cstdint>

// Problem constants
#define BATCH 8
#define NNODE 2048
#define DIM   256
#define MROWS (BATCH * NNODE)   // 16384

// -------------------- scratch (no allocations allowed) --------------------
__device__ float g_H[(size_t)MROWS * DIM];   // 16 MB fp32
__device__ float g_s1[MROWS];
__device__ float g_s2[MROWS];
__device__ __nv_bfloat16 g_Xhi[(size_t)MROWS * DIM];
__device__ __nv_bfloat16 g_Xlo[(size_t)MROWS * DIM];
__device__ __nv_bfloat16 g_Whi[DIM * DIM];
__device__ __nv_bfloat16 g_Wlo[DIM * DIM];

// ============================================================================
// Helpers (base sm_103 target: ldmatrix + mma.sync + cp.async; NO tcgen05)
// ============================================================================
__device__ __forceinline__ uint32_t smem_u32(const void* p) {
    uint32_t a;
    asm("{ .reg .u64 t; cvta.to.shared.u64 t, %1; cvt.u32.u64 %0, t; }"
        : "=r"(a) : "l"(p));
    return a;
}

__device__ __forceinline__ void cp16(uint32_t dst, const void* src) {
    asm volatile("cp.async.cg.shared.global [%0], [%1], 16;"
                 :: "r"(dst), "l"(src));
}
#define CP_COMMIT() asm volatile("cp.async.commit_group;" ::: "memory")
#define CP_WAIT0()  asm volatile("cp.async.wait_group 0;" ::: "memory")

__device__ __forceinline__ void ldm_x4(uint32_t* r, uint32_t addr) {
    asm volatile("ldmatrix.sync.aligned.m8n8.x4.shared.b16 {%0,%1,%2,%3}, [%4];"
        : "=r"(r[0]), "=r"(r[1]), "=r"(r[2]), "=r"(r[3]) : "r"(addr));
}

__device__ __forceinline__ void mma_bf16(float* c, const uint32_t* a,
                                         const uint32_t* b) {
    asm volatile(
        "mma.sync.aligned.m16n8k16.row.col.f32.bf16.bf16.f32 "
        "{%0,%1,%2,%3}, {%4,%5,%6,%7}, {%8,%9}, {%0,%1,%2,%3};"
        : "+f"(c[0]), "+f"(c[1]), "+f"(c[2]), "+f"(c[3])
        : "r"(a[0]), "r"(a[1]), "r"(a[2]), "r"(a[3]), "r"(b[0]), "r"(b[1]));
}

// bf16 split: hi = bf16(x), lo = bf16(x - hi); packs (e0, e1) pairs.
__device__ __forceinline__ void split_pair(float e0, float e1,
                                           uint32_t& h, uint32_t& l) {
    asm("cvt.rn.bf16x2.f32 %0, %1, %2;" : "=r"(h) : "f"(e1), "f"(e0));
    __nv_bfloat162 hb = *(__nv_bfloat162*)&h;
    float r0 = e0 - __bfloat162float(hb.x);
    float r1 = e1 - __bfloat162float(hb.y);
    asm("cvt.rn.bf16x2.f32 %0, %1, %2;" : "=r"(l) : "f"(r1), "f"(r0));
}

// ============================================================================
// Kernel 0: fp32 -> split-bf16 conversion
// ============================================================================
__global__ void __launch_bounds__(256)
convert_split(const float* __restrict__ src, __nv_bfloat16* __restrict__ hi,
              __nv_bfloat16* __restrict__ lo)
{
    const int idx = blockIdx.x * 256 + threadIdx.x;
    const float* s = src + (size_t)idx * 8;
    float4 v0 = *(const float4*)(s);
    float4 v1 = *(const float4*)(s + 4);
    uint32_t h[4], l[4];
    split_pair(v0.x, v0.y, h[0], l[0]);
    split_pair(v0.z, v0.w, h[1], l[1]);
    split_pair(v1.x, v1.y, h[2], l[2]);
    split_pair(v1.z, v1.w, h[3], l[3]);
    uint4* hp = (uint4*)(hi + (size_t)idx * 8);
    uint4* lp = (uint4*)(lo + (size_t)idx * 8);
    *hp = make_uint4(h[0], h[1], h[2], h[3]);
    *lp = make_uint4(l[0], l[1], l[2], l[3]);
}

// ============================================================================
// Kernel 1: split-bf16 HMMA GEMM, re-tiled for 2 CTAs/SM.
// CTA 128x64, 8 warps (4x2), warp tile 32x32, K-step 16, 2-stage cp.async.
// D = Ahi*Bhi + Ahi*Blo + Alo*Bhi (fp32 accumulate).
// ============================================================================
#define SROW 24
// per-stage tile bytes: A = 128*SROW*2, B = 64*SROW*2
#define A_STG (128 * SROW * 2)
#define B_STG (64 * SROW * 2)

__global__ void __launch_bounds__(256, 2)
gemm_h_mma(const __nv_bfloat16* __restrict__ Xhi,
           const __nv_bfloat16* __restrict__ Xlo,
           const __nv_bfloat16* __restrict__ Whi,
           const __nv_bfloat16* __restrict__ Wlo,
           const float* __restrict__ bias)
{
    __shared__ __nv_bfloat16 sAhi[2][128][SROW];   // 12 KB
    __shared__ __nv_bfloat16 sAlo[2][128][SROW];   // 12 KB
    __shared__ __nv_bfloat16 sBhi[2][64][SROW];    // 6 KB
    __shared__ __nv_bfloat16 sBlo[2][64][SROW];    // 6 KB  -> 36 KB total

    const int tid   = threadIdx.x;
    const int wid   = tid >> 5;
    const int lane  = tid & 31;
    const int cta_m = blockIdx.x * 128;
    const int cta_n = blockIdx.y * 64;

    const int wm = (wid >> 1) * 32;   // 4 M positions
    const int wn = (wid & 1) * 32;    // 2 N positions

    // A loader: 256 threads cover 128 rows x 2 halves (1 cp16 per matrix)
    const int arow_ = tid >> 1;
    const int ahalf = (tid & 1) * 8;
    const __nv_bfloat16* srcAhi = Xhi + (size_t)(cta_m + arow_) * DIM + ahalf;
    const __nv_bfloat16* srcAlo = Xlo + (size_t)(cta_m + arow_) * DIM + ahalf;
    const uint32_t dAhi = smem_u32(&sAhi[0][arow_][ahalf]);
    const uint32_t dAlo = smem_u32(&sAlo[0][arow_][ahalf]);
    // B loader: first 128 threads cover 64 rows x 2 halves
    const bool bldr  = tid < 128;
    const int brow_  = (tid & 127) >> 1;
    const int bhalf  = (tid & 1) * 8;
    const __nv_bfloat16* srcBhi = Whi + (size_t)(cta_n + brow_) * DIM + bhalf;
    const __nv_bfloat16* srcBlo = Wlo + (size_t)(cta_n + brow_) * DIM + bhalf;
    const uint32_t dBhi = smem_u32(&sBhi[0][brow_][bhalf]);
    const uint32_t dBlo = smem_u32(&sBlo[0][brow_][bhalf]);

    // ldmatrix addresses for stage 0
    uint32_t aAhi[2], aAlo[2];
#pragma unroll
    for (int mt = 0; mt < 2; mt++) {
        int row = wm + mt * 16 + (lane & 15);
        int kh  = (lane >> 4) * 8;
        aAhi[mt] = smem_u32(&sAhi[0][row][kh]);
        aAlo[mt] = smem_u32(&sAlo[0][row][kh]);
    }
    uint32_t bBhi[2], bBlo[2];
#pragma unroll
    for (int nt2 = 0; nt2 < 2; nt2++) {
        int nr = wn + nt2 * 16 + ((lane >> 4) * 8) + (lane & 7);
        int kh = ((lane >> 3) & 1) * 8;
        bBhi[nt2] = smem_u32(&sBhi[0][nr][kh]);
        bBlo[nt2] = smem_u32(&sBlo[0][nr][kh]);
    }

    float acc[2][4][4];
#pragma unroll
    for (int mt = 0; mt < 2; mt++)
#pragma unroll
        for (int nt = 0; nt < 4; nt++)
#pragma unroll
            for (int c = 0; c < 4; c++) acc[mt][nt][c] = 0.f;

    // prologue
    cp16(dAhi, srcAhi); cp16(dAlo, srcAlo);
    if (bldr) { cp16(dBhi, srcBhi); cp16(dBlo, srcBlo); }
    CP_COMMIT();

#pragma unroll 1
    for (int ks = 0; ks < DIM / 16; ks++) {
        CP_WAIT0();
        __syncthreads();

        if (ks + 1 < DIM / 16) {
            const int ko = (ks + 1) * 16;
            const uint32_t pa = (uint32_t)(((ks + 1) & 1) * A_STG);
            const uint32_t pb = (uint32_t)(((ks + 1) & 1) * B_STG);
            cp16(dAhi + pa, srcAhi + ko); cp16(dAlo + pa, srcAlo + ko);
            if (bldr) { cp16(dBhi + pb, srcBhi + ko); cp16(dBlo + pb, srcBlo + ko); }
        }
        CP_COMMIT();

        const uint32_t sa = (uint32_t)((ks & 1) * A_STG);
        const uint32_t sb = (uint32_t)((ks & 1) * B_STG);

        uint32_t fAhi[2][4], fAlo[2][4];
#pragma unroll
        for (int mt = 0; mt < 2; mt++) {
            ldm_x4(fAhi[mt], aAhi[mt] + sa);
            ldm_x4(fAlo[mt], aAlo[mt] + sa);
        }
        uint32_t fBhi[4][2], fBlo[4][2];
#pragma unroll
        for (int nt2 = 0; nt2 < 2; nt2++) {
            uint32_t r[4];
            ldm_x4(r, bBhi[nt2] + sb);
            fBhi[nt2 * 2][0] = r[0]; fBhi[nt2 * 2][1] = r[1];
            fBhi[nt2 * 2 + 1][0] = r[2]; fBhi[nt2 * 2 + 1][1] = r[3];
            ldm_x4(r, bBlo[nt2] + sb);
            fBlo[nt2 * 2][0] = r[0]; fBlo[nt2 * 2][1] = r[1];
            fBlo[nt2 * 2 + 1][0] = r[2]; fBlo[nt2 * 2 + 1][1] = r[3];
        }

#pragma unroll
        for (int mt = 0; mt < 2; mt++)
#pragma unroll
            for (int nt = 0; nt < 4; nt++) {
                mma_bf16(acc[mt][nt], fAhi[mt], fBhi[nt]);
                mma_bf16(acc[mt][nt], fAhi[mt], fBlo[nt]);
                mma_bf16(acc[mt][nt], fAlo[mt], fBhi[nt]);
            }
    }

    // ---- epilogue: +bias, store fp32 H ----
    const int gid = lane >> 2;
    const int tig = lane & 3;
#pragma unroll
    for (int nt = 0; nt < 4; nt++) {
        const int col = cta_n + wn + nt * 8 + tig * 2;
        const float2 bv = *(const float2*)(bias + col);
#pragma unroll
        for (int mt = 0; mt < 2; mt++) {
            const int m0 = cta_m + wm + mt * 16 + gid;
            float2 v0 = make_float2(acc[mt][nt][0] + bv.x, acc[mt][nt][1] + bv.y);
            float2 v1 = make_float2(acc[mt][nt][2] + bv.x, acc[mt][nt][3] + bv.y);
            *(float2*)(g_H + (size_t)m0 * DIM + col)       = v0;
            *(float2*)(g_H + (size_t)(m0 + 8) * DIM + col) = v1;
        }
    }
}

// ============================================================================
// Kernel 2: s1/s2 projections (unchanged)
// ============================================================================
__global__ void __launch_bounds__(256)
sproj_kernel(const float* __restrict__ a1, const float* __restrict__ a2,
             const float* __restrict__ att_b)
{
    const int row  = blockIdx.x * 8 + (threadIdx.x >> 5);
    const int lane = threadIdx.x & 31;
    const float* hr = g_H + (size_t)row * DIM + lane * 8;

    float4 h0 = *(const float4*)(hr);
    float4 h1 = *(const float4*)(hr + 4);
    float4 p0 = *(const float4*)(a1 + lane * 8);
    float4 p1 = *(const float4*)(a1 + lane * 8 + 4);
    float4 q0 = *(const float4*)(a2 + lane * 8);
    float4 q1 = *(const float4*)(a2 + lane * 8 + 4);

    float d1 = h0.x * p0.x + h0.y * p0.y + h0.z * p0.z + h0.w * p0.w
             + h1.x * p1.x + h1.y * p1.y + h1.z * p1.z + h1.w * p1.w;
    float d2 = h0.x * q0.x + h0.y * q0.y + h0.z * q0.z + h0.w * q0.w
             + h1.x * q1.x + h1.y * q1.y + h1.z * q1.z + h1.w * q1.w;

#pragma unroll
    for (int o = 16; o; o >>= 1) {
        d1 += __shfl_xor_sync(0xffffffffu, d1, o);
        d2 += __shfl_xor_sync(0xffffffffu, d2, o);
    }
    if (lane == 0) {
        g_s1[row] = d1 + att_b[0];
        g_s2[row] = d2;
    }
}

// ============================================================================
// Kernel 3: attention + aggregation — EXACT round-6 best (129.5us config).
// ============================================================================
__global__ void __launch_bounds__(256)
attn_agg_kernel(const float* __restrict__ adj, const float* __restrict__ mask,
                float* __restrict__ out)
{
    const int i   = blockIdx.x;
    const int b   = blockIdx.y;
    const int tid = threadIdx.x;
    const int row = b * NNODE + i;

    __shared__ float wbuf[NNODE];
    __shared__ int   jbuf[NNODE];
    __shared__ float sred[4][DIM];
    __shared__ int   s_cnt;
    __shared__ float s_sum;

    const float mi = mask[row];
    float* orow = out + (size_t)row * DIM;
    if (mi == 0.f) {
        orow[tid] = 0.f;
        return;
    }

    if (tid == 0) { s_cnt = 0; s_sum = 0.f; }
    __syncthreads();

    const float* arow = adj + (size_t)row * NNODE;
    const float  s1i  = g_s1[row];
    const float* mrow = mask + b * NNODE;
    const float* s2b  = g_s2 + b * NNODE;
    const int lane = tid & 31;

    float4 av[2], mv[2], sv[2];
#pragma unroll
    for (int u = 0; u < 2; u++) {
        int j0 = tid * 4 + u * 1024;
        av[u] = *(const float4*)(arow + j0);
        mv[u] = *(const float4*)(mrow + j0);
        sv[u] = *(const float4*)(s2b + j0);
    }

    float w[8];
    float psum = 0.f;
#pragma unroll
    for (int u = 0; u < 2; u++) {
        const float* ap = (const float*)&av[u];
        const float* mp = (const float*)&mv[u];
        const float* sp = (const float*)&sv[u];
#pragma unroll
        for (int e = 0; e < 4; e++) {
            float ww = 0.f;
            if (ap[e] != 0.f && mp[e] != 0.f) {
                float lg = s1i + sp[e];
                ww = ap[e] * mp[e] / (1.f + __expf(-lg));
            }
            w[u * 4 + e] = ww;
            psum += ww;
        }
    }

#pragma unroll
    for (int e = 0; e < 8; e++) {
        unsigned bal = __ballot_sync(0xffffffffu, w[e] != 0.f);
        if (bal) {
            int leader = __ffs(bal) - 1;
            int base = 0;
            if (lane == leader) base = atomicAdd(&s_cnt, __popc(bal));
            base = __shfl_sync(0xffffffffu, base, leader);
            if (w[e] != 0.f) {
                int rank = __popc(bal & ((1u << lane) - 1u));
                wbuf[base + rank] = w[e];
                jbuf[base + rank] = tid * 4 + (e >> 2) * 1024 + (e & 3);
            }
        }
    }

#pragma unroll
    for (int o = 16; o; o >>= 1) psum += __shfl_xor_sync(0xffffffffu, psum, o);
    if (lane == 0) atomicAdd(&s_sum, psum);
    __syncthreads();

    const int n   = s_cnt;
    const float inv = 1.f / (s_sum + 1e-8f);
    const float* Hb = g_H + (size_t)b * NNODE * DIM;

    const int g  = tid >> 6;
    const int c4 = (tid & 63) * 4;

    float4 acc = make_float4(0.f, 0.f, 0.f, 0.f);
    int k = g;
    for (; k + 4 < n; k += 8) {
        int   ja = jbuf[k],   jc = jbuf[k + 4];
        float wa = wbuf[k],   wc = wbuf[k + 4];
        float4 ha = *(const float4*)(Hb + (size_t)ja * DIM + c4);
        float4 hc = *(const float4*)(Hb + (size_t)jc * DIM + c4);
        acc.x += wa * ha.x + wc * hc.x;
        acc.y += wa * ha.y + wc * hc.y;
        acc.z += wa * ha.z + wc * hc.z;
        acc.w += wa * ha.w + wc * hc.w;
    }
    if (k < n) {
        int   ja = jbuf[k];
        float wa = wbuf[k];
        float4 ha = *(const float4*)(Hb + (size_t)ja * DIM + c4);
        acc.x += wa * ha.x; acc.y += wa * ha.y;
        acc.z += wa * ha.z; acc.w += wa * ha.w;
    }

    *(float4*)&sred[g][c4] = acc;
    __syncthreads();

    float r = sred[0][tid] + sred[1][tid] + sred[2][tid] + sred[3][tid];
    orow[tid] = r * inv;
}

// ============================================================================
// Launch
// ============================================================================
extern "C" void kernel_launch(void* const* d_in, const int* in_sizes, int n_in,
                              void* d_out, int out_size)
{
    const float* x     = (const float*)d_in[0];
    const float* adj   = (const float*)d_in[1];
    const float* mask  = (const float*)d_in[2];
    const float* W     = (const float*)d_in[3];
    const float* bias  = (const float*)d_in[4];
    const float* a1    = (const float*)d_in[5];
    const float* a2    = (const float*)d_in[6];
    const float* att_b = (const float*)d_in[7];
    float* out = (float*)d_out;

    __nv_bfloat16 *xhi, *xlo, *whi, *wlo;
    cudaGetSymbolAddress((void**)&xhi, g_Xhi);
    cudaGetSymbolAddress((void**)&xlo, g_Xlo);
    cudaGetSymbolAddress((void**)&whi, g_Whi);
    cudaGetSymbolAddress((void**)&wlo, g_Wlo);

    convert_split<<<(MROWS * DIM) / (256 * 8), 256>>>(x, xhi, xlo);
    convert_split<<<(DIM * DIM) / (256 * 8), 256>>>(W, whi, wlo);

    dim3 g1(MROWS / 128, DIM / 64);       // (128, 4)
    gemm_h_mma<<<g1, 256>>>(xhi, xlo, whi, wlo, bias);

    sproj_kernel<<<MROWS / 8, 256>>>(a1, a2, att_b);

    dim3 g3(NNODE, BATCH);                // (2048, 8)
    attn_agg_kernel<<<g3, 256>>>(adj, mask, out);
}

// round 11
// speedup vs baseline: 1.1957x; 1.0452x over previous
#include <cuda_runtime.h>
#include <cuda_bf16.h>
#include <cstdint>

// Problem constants
#define BATCH 8
#define NNODE 2048
#define DIM   256
#define MROWS (BATCH * NNODE)   // 16384
#define MTILES (MROWS / 16)     // 1024
#define KSTEPS (DIM / 16)       // 16
#define NPAIRS (DIM / 16)       // 16 (n16 pairs across OUT_DIM)

// -------------------- scratch (no allocations allowed) --------------------
__device__ float g_H[(size_t)MROWS * DIM];   // 16 MB fp32
__device__ float g_s1[MROWS];
__device__ float g_s2[MROWS];
// Fragment-order operands for mma.sync m16n8k16 (canonical PTX lane layout):
// AF[(mtile*16 + ks)*32 + lane] = uint4(a0,a1,a2,a3)  (bf16x2 each)
// BF[(pair *16 + ks)*32 + lane] = uint4(b0_t0,b1_t0,b0_t1,b1_t1)
__device__ uint4 g_AFhi[(size_t)MTILES * KSTEPS * 32];   // 8 MB
__device__ uint4 g_AFlo[(size_t)MTILES * KSTEPS * 32];   // 8 MB
__device__ uint4 g_BFhi[NPAIRS * KSTEPS * 32];           // 128 KB
__device__ uint4 g_BFlo[NPAIRS * KSTEPS * 32];           // 128 KB

// ============================================================================
// Helpers (base sm_103 target: mma.sync; NO tcgen05, NO smem staging)
// ============================================================================
__device__ __forceinline__ void mma_bf16(float* c, const uint32_t* a,
                                         const uint32_t* b) {
    asm volatile(
        "mma.sync.aligned.m16n8k16.row.col.f32.bf16.bf16.f32 "
        "{%0,%1,%2,%3}, {%4,%5,%6,%7}, {%8,%9}, {%0,%1,%2,%3};"
        : "+f"(c[0]), "+f"(c[1]), "+f"(c[2]), "+f"(c[3])
        : "r"(a[0]), "r"(a[1]), "r"(a[2]), "r"(a[3]), "r"(b[0]), "r"(b[1]));
}

// bf16 split: hi = bf16(x), lo = bf16(x - hi); packs (e0, e1) -> bf16x2.
__device__ __forceinline__ void split_pair(float e0, float e1,
                                           uint32_t& h, uint32_t& l) {
    asm("cvt.rn.bf16x2.f32 %0, %1, %2;" : "=r"(h) : "f"(e1), "f"(e0));
    __nv_bfloat162 hb = *(__nv_bfloat162*)&h;
    float r0 = e0 - __bfloat162float(hb.x);
    float r1 = e1 - __bfloat162float(hb.y);
    asm("cvt.rn.bf16x2.f32 %0, %1, %2;" : "=r"(l) : "f"(r1), "f"(r0));
}

// ============================================================================
// Kernel 0a: X -> A-fragments (split bf16 hi/lo) in canonical mma layout.
// One warp per (mtile, kstep). Lane (g=lane>>2, tig=lane&3):
//   a0=(r0,c0) a1=(r0+8,c0) a2=(r0,c0+8) a3=(r0+8,c0+8), pairs of 2 cols.
// ============================================================================
__global__ void __launch_bounds__(256)
convert_xfrag(const float* __restrict__ X)
{
    const int gw   = blockIdx.x * 8 + (threadIdx.x >> 5);   // warp id
    const int lane = threadIdx.x & 31;
    const int mtile = gw >> 4;
    const int ks    = gw & 15;
    const int g   = lane >> 2;
    const int tig = lane & 3;
    const int r0 = mtile * 16 + g;
    const int c0 = ks * 16 + tig * 2;

    float2 p00 = *(const float2*)(X + (size_t)r0 * DIM + c0);
    float2 p10 = *(const float2*)(X + (size_t)(r0 + 8) * DIM + c0);
    float2 p01 = *(const float2*)(X + (size_t)r0 * DIM + c0 + 8);
    float2 p11 = *(const float2*)(X + (size_t)(r0 + 8) * DIM + c0 + 8);

    uint32_t h[4], l[4];
    split_pair(p00.x, p00.y, h[0], l[0]);
    split_pair(p10.x, p10.y, h[1], l[1]);
    split_pair(p01.x, p01.y, h[2], l[2]);
    split_pair(p11.x, p11.y, h[3], l[3]);

    const size_t idx = (size_t)gw * 32 + lane;
    g_AFhi[idx] = make_uint4(h[0], h[1], h[2], h[3]);
    g_AFlo[idx] = make_uint4(l[0], l[1], l[2], l[3]);
}

// ============================================================================
// Kernel 0b: W -> B-fragments. One warp per (n16-pair, kstep).
// Tile t (n8): b0 = W[n][k0],W[n][k0+1]; b1 = W[n][k0+8],W[n][k0+9], n=base+g.
// ============================================================================
__global__ void __launch_bounds__(256)
convert_wfrag(const float* __restrict__ W)
{
    const int gw   = blockIdx.x * 8 + (threadIdx.x >> 5);   // 0..255
    const int lane = threadIdx.x & 31;
    const int pair = gw >> 4;
    const int ks   = gw & 15;
    const int g   = lane >> 2;
    const int tig = lane & 3;
    const int n0 = pair * 16 + g;
    const int n1 = n0 + 8;
    const int k0 = ks * 16 + tig * 2;

    float2 q00 = *(const float2*)(W + (size_t)n0 * DIM + k0);
    float2 q01 = *(const float2*)(W + (size_t)n0 * DIM + k0 + 8);
    float2 q10 = *(const float2*)(W + (size_t)n1 * DIM + k0);
    float2 q11 = *(const float2*)(W + (size_t)n1 * DIM + k0 + 8);

    uint32_t h[4], l[4];
    split_pair(q00.x, q00.y, h[0], l[0]);   // b0 of tile0
    split_pair(q01.x, q01.y, h[1], l[1]);   // b1 of tile0
    split_pair(q10.x, q10.y, h[2], l[2]);   // b0 of tile1
    split_pair(q11.x, q11.y, h[3], l[3]);   // b1 of tile1

    const size_t idx = (size_t)gw * 32 + lane;
    g_BFhi[idx] = make_uint4(h[0], h[1], h[2], h[3]);
    g_BFlo[idx] = make_uint4(l[0], l[1], l[2], l[3]);
}

// ============================================================================
// Kernel 1: fragment-direct HMMA GEMM. CTA 128x128, 8 warps, warp 64x32.
// No smem, no cp.async, no syncthreads: 12 LDG.128/warp/k-step + 48 MMAs.
// A (hi,lo) register-prefetched 1 k-step ahead; B is L1/L2-resident.
// D = Ahi*Bhi + Ahi*Blo + Alo*Bhi (fp32 accumulate).
// ============================================================================
__global__ void __launch_bounds__(256, 1)
gemm_h_frag(const float* __restrict__ bias)
{
    const int tid  = threadIdx.x;
    const int wid  = tid >> 5;
    const int lane = tid & 31;
    const int cta_m = blockIdx.x * 128;
    const int cta_n = blockIdx.y * 128;

    const int wm = (wid & 1) * 64;    // warp M offset
    const int wn = (wid >> 1) * 32;   // warp N offset

    const int mt_base = (cta_m + wm) >> 4;   // 4 consecutive m16 tiles
    const int np_base = (cta_n + wn) >> 4;   // 2 consecutive n16 pairs

    const uint4* Ah = g_AFhi + (size_t)mt_base * 512 + lane;  // mtile stride 16*32
    const uint4* Al = g_AFlo + (size_t)mt_base * 512 + lane;
    const uint4* Bh = g_BFhi + (size_t)np_base * 512 + lane;
    const uint4* Bl = g_BFlo + (size_t)np_base * 512 + lane;

    float acc[4][4][4];
#pragma unroll
    for (int mt = 0; mt < 4; mt++)
#pragma unroll
        for (int nt = 0; nt < 4; nt++)
#pragma unroll
            for (int c = 0; c < 4; c++) acc[mt][nt][c] = 0.f;

    // preload k-step 0
    uint4 cAh[4], cAl[4], cBh[2], cBl[2];
#pragma unroll
    for (int mt = 0; mt < 4; mt++) { cAh[mt] = Ah[mt * 512]; cAl[mt] = Al[mt * 512]; }
#pragma unroll
    for (int p = 0; p < 2; p++)    { cBh[p] = Bh[p * 512];   cBl[p] = Bl[p * 512]; }

#pragma unroll 1
    for (int ks = 0; ks < KSTEPS; ks++) {
        // prefetch next k-step (registers; overlaps the 48 MMAs below)
        uint4 nAh[4], nAl[4], nBh[2], nBl[2];
        if (ks + 1 < KSTEPS) {
            const int o = (ks + 1) * 32;
#pragma unroll
            for (int mt = 0; mt < 4; mt++) {
                nAh[mt] = Ah[mt * 512 + o];
                nAl[mt] = Al[mt * 512 + o];
            }
#pragma unroll
            for (int p = 0; p < 2; p++) {
                nBh[p] = Bh[p * 512 + o];
                nBl[p] = Bl[p * 512 + o];
            }
        }

#pragma unroll
        for (int mt = 0; mt < 4; mt++) {
            const uint32_t* ah = (const uint32_t*)&cAh[mt];
            const uint32_t* al = (const uint32_t*)&cAl[mt];
#pragma unroll
            for (int nt = 0; nt < 4; nt++) {
                const uint32_t* qh = (const uint32_t*)&cBh[nt >> 1];
                const uint32_t* ql = (const uint32_t*)&cBl[nt >> 1];
                uint32_t bh[2] = { qh[(nt & 1) * 2], qh[(nt & 1) * 2 + 1] };
                uint32_t bl[2] = { ql[(nt & 1) * 2], ql[(nt & 1) * 2 + 1] };
                mma_bf16(acc[mt][nt], ah, bh);
                mma_bf16(acc[mt][nt], ah, bl);
                mma_bf16(acc[mt][nt], al, bh);
            }
        }

        if (ks + 1 < KSTEPS) {
#pragma unroll
            for (int mt = 0; mt < 4; mt++) { cAh[mt] = nAh[mt]; cAl[mt] = nAl[mt]; }
#pragma unroll
            for (int p = 0; p < 2; p++)    { cBh[p] = nBh[p];   cBl[p] = nBl[p]; }
        }
    }

    // ---- epilogue: +bias, store fp32 H (canonical C layout) ----
    const int gid = lane >> 2;
    const int tig = lane & 3;
#pragma unroll
    for (int nt = 0; nt < 4; nt++) {
        const int col = cta_n + wn + nt * 8 + tig * 2;
        const float2 bv = *(const float2*)(bias + col);
#pragma unroll
        for (int mt = 0; mt < 4; mt++) {
            const int m0 = cta_m + wm + mt * 16 + gid;
            float2 v0 = make_float2(acc[mt][nt][0] + bv.x, acc[mt][nt][1] + bv.y);
            float2 v1 = make_float2(acc[mt][nt][2] + bv.x, acc[mt][nt][3] + bv.y);
            *(float2*)(g_H + (size_t)m0 * DIM + col)       = v0;
            *(float2*)(g_H + (size_t)(m0 + 8) * DIM + col) = v1;
        }
    }
}

// ============================================================================
// Kernel 2: s1/s2 projections (unchanged)
// ============================================================================
__global__ void __launch_bounds__(256)
sproj_kernel(const float* __restrict__ a1, const float* __restrict__ a2,
             const float* __restrict__ att_b)
{
    const int row  = blockIdx.x * 8 + (threadIdx.x >> 5);
    const int lane = threadIdx.x & 31;
    const float* hr = g_H + (size_t)row * DIM + lane * 8;

    float4 h0 = *(const float4*)(hr);
    float4 h1 = *(const float4*)(hr + 4);
    float4 p0 = *(const float4*)(a1 + lane * 8);
    float4 p1 = *(const float4*)(a1 + lane * 8 + 4);
    float4 q0 = *(const float4*)(a2 + lane * 8);
    float4 q1 = *(const float4*)(a2 + lane * 8 + 4);

    float d1 = h0.x * p0.x + h0.y * p0.y + h0.z * p0.z + h0.w * p0.w
             + h1.x * p1.x + h1.y * p1.y + h1.z * p1.z + h1.w * p1.w;
    float d2 = h0.x * q0.x + h0.y * q0.y + h0.z * q0.z + h0.w * q0.w
             + h1.x * q1.x + h1.y * q1.y + h1.z * q1.z + h1.w * q1.w;

#pragma unroll
    for (int o = 16; o; o >>= 1) {
        d1 += __shfl_xor_sync(0xffffffffu, d1, o);
        d2 += __shfl_xor_sync(0xffffffffu, d2, o);
    }
    if (lane == 0) {
        g_s1[row] = d1 + att_b[0];
        g_s2[row] = d2;
    }
}

// ============================================================================
// Kernel 3: attention + aggregation — EXACT 129.5us-best config (unchanged).
// ============================================================================
__global__ void __launch_bounds__(256)
attn_agg_kernel(const float* __restrict__ adj, const float* __restrict__ mask,
                float* __restrict__ out)
{
    const int i   = blockIdx.x;
    const int b   = blockIdx.y;
    const int tid = threadIdx.x;
    const int row = b * NNODE + i;

    __shared__ float wbuf[NNODE];
    __shared__ int   jbuf[NNODE];
    __shared__ float sred[4][DIM];
    __shared__ int   s_cnt;
    __shared__ float s_sum;

    const float mi = mask[row];
    float* orow = out + (size_t)row * DIM;
    if (mi == 0.f) {
        orow[tid] = 0.f;
        return;
    }

    if (tid == 0) { s_cnt = 0; s_sum = 0.f; }
    __syncthreads();

    const float* arow = adj + (size_t)row * NNODE;
    const float  s1i  = g_s1[row];
    const float* mrow = mask + b * NNODE;
    const float* s2b  = g_s2 + b * NNODE;
    const int lane = tid & 31;

    float4 av[2], mv[2], sv[2];
#pragma unroll
    for (int u = 0; u < 2; u++) {
        int j0 = tid * 4 + u * 1024;
        av[u] = *(const float4*)(arow + j0);
        mv[u] = *(const float4*)(mrow + j0);
        sv[u] = *(const float4*)(s2b + j0);
    }

    float w[8];
    float psum = 0.f;
#pragma unroll
    for (int u = 0; u < 2; u++) {
        const float* ap = (const float*)&av[u];
        const float* mp = (const float*)&mv[u];
        const float* sp = (const float*)&sv[u];
#pragma unroll
        for (int e = 0; e < 4; e++) {
            float ww = 0.f;
            if (ap[e] != 0.f && mp[e] != 0.f) {
                float lg = s1i + sp[e];
                ww = ap[e] * mp[e] / (1.f + __expf(-lg));
            }
            w[u * 4 + e] = ww;
            psum += ww;
        }
    }

#pragma unroll
    for (int e = 0; e < 8; e++) {
        unsigned bal = __ballot_sync(0xffffffffu, w[e] != 0.f);
        if (bal) {
            int leader = __ffs(bal) - 1;
            int base = 0;
            if (lane == leader) base = atomicAdd(&s_cnt, __popc(bal));
            base = __shfl_sync(0xffffffffu, base, leader);
            if (w[e] != 0.f) {
                int rank = __popc(bal & ((1u << lane) - 1u));
                wbuf[base + rank] = w[e];
                jbuf[base + rank] = tid * 4 + (e >> 2) * 1024 + (e & 3);
            }
        }
    }

#pragma unroll
    for (int o = 16; o; o >>= 1) psum += __shfl_xor_sync(0xffffffffu, psum, o);
    if (lane == 0) atomicAdd(&s_sum, psum);
    __syncthreads();

    const int n   = s_cnt;
    const float inv = 1.f / (s_sum + 1e-8f);
    const float* Hb = g_H + (size_t)b * NNODE * DIM;

    const int g  = tid >> 6;
    const int c4 = (tid & 63) * 4;

    float4 acc = make_float4(0.f, 0.f, 0.f, 0.f);
    int k = g;
    for (; k + 4 < n; k += 8) {
        int   ja = jbuf[k],   jc = jbuf[k + 4];
        float wa = wbuf[k],   wc = wbuf[k + 4];
        float4 ha = *(const float4*)(Hb + (size_t)ja * DIM + c4);
        float4 hc = *(const float4*)(Hb + (size_t)jc * DIM + c4);
        acc.x += wa * ha.x + wc * hc.x;
        acc.y += wa * ha.y + wc * hc.y;
        acc.z += wa * ha.z + wc * hc.z;
        acc.w += wa * ha.w + wc * hc.w;
    }
    if (k < n) {
        int   ja = jbuf[k];
        float wa = wbuf[k];
        float4 ha = *(const float4*)(Hb + (size_t)ja * DIM + c4);
        acc.x += wa * ha.x; acc.y += wa * ha.y;
        acc.z += wa * ha.z; acc.w += wa * ha.w;
    }

    *(float4*)&sred[g][c4] = acc;
    __syncthreads();

    float r = sred[0][tid] + sred[1][tid] + sred[2][tid] + sred[3][tid];
    orow[tid] = r * inv;
}

// ============================================================================
// Launch
// ============================================================================
extern "C" void kernel_launch(void* const* d_in, const int* in_sizes, int n_in,
                              void* d_out, int out_size)
{
    const float* x     = (const float*)d_in[0];
    const float* adj   = (const float*)d_in[1];
    const float* mask  = (const float*)d_in[2];
    const float* W     = (const float*)d_in[3];
    const float* bias  = (const float*)d_in[4];
    const float* a1    = (const float*)d_in[5];
    const float* a2    = (const float*)d_in[6];
    const float* att_b = (const float*)d_in[7];
    float* out = (float*)d_out;

    convert_xfrag<<<(MTILES * KSTEPS) / 8, 256>>>(x);   // 2048 blocks
    convert_wfrag<<<(NPAIRS * KSTEPS) / 8, 256>>>(W);   // 32 blocks

    dim3 g1(MROWS / 128, DIM / 128);      // (128, 2)
    gemm_h_frag<<<g1, 256>>>(bias);

    sproj_kernel<<<MROWS / 8, 256>>>(a1, a2, att_b);

    dim3 g3(NNODE, BATCH);                // (2048, 8)
    attn_agg_kernel<<<g3, 256>>>(adj, mask, out);
}